// round 6
// baseline (speedup 1.0000x reference)
#include <cuda_runtime.h>
#include <cstdint>
#include <cstddef>

#define BB 8
#define SS 2048
#define TT 1024
#define EE 1024
#define HH 16
#define DD 64
#define CC 768

// Scratch (device globals: allocation-free rule)
__device__ float  g_q   [(size_t)BB*HH*SS*DD];   // [B,H,S,D]  64 MB
__device__ float  g_k   [(size_t)BB*HH*DD*TT];   // [B,H,D,T]  32 MB
__device__ float  g_v   [(size_t)BB*HH*TT*DD];   // [B,H,T,D]  32 MB
__device__ float  g_ao  [(size_t)BB*SS*EE];      // attn out [B,S,E] 64 MB
__device__ float  g_praw[(size_t)BB*HH*SS*TT];   // raw scaled scores [B,H,S,T] 1 GiB
__device__ float2 g_stat[(size_t)BB*HH*SS];      // per-row (m, invZ/H) 2 MB

// ---- packed f32x2 helpers ----
__device__ __forceinline__ unsigned long long pack2(float lo, float hi) {
    unsigned long long r;
    asm("mov.b64 %0, {%1, %2};" : "=l"(r) : "f"(lo), "f"(hi));
    return r;
}
__device__ __forceinline__ void unpack2(unsigned long long v, float& lo, float& hi) {
    asm("mov.b64 {%0, %1}, %2;" : "=f"(lo), "=f"(hi) : "l"(v));
}
__device__ __forceinline__ void ffma2(unsigned long long& d, unsigned long long a, unsigned long long b) {
    asm("fma.rn.f32x2 %0, %1, %2, %0;" : "+l"(d) : "l"(a), "l"(b));
}
__device__ __forceinline__ void fmul2(unsigned long long& d, unsigned long long a) {
    asm("mul.rn.f32x2 %0, %0, %1;" : "+l"(d) : "l"(a));
}

// ============================================================================
// GEMM v2: C[M,N] = A[M,K] @ W[K,N] + bias, head-remapped output.
// 128x64 CTA tile, 256 threads, 8(m)x4(n) micro-tile, K-chunk 32.
// A stored DUPLICATED in smem: As2[k][2m]=As2[k][2m+1]=a  -> LDS.64 gives (a,a)
// directly, zero mov.b64 packs in the inner loop. B read as natural f32x2
// pairs via LDS.128.
// mode 0: plain row-major [M,N]
// mode 1: out[((b*H + h)*len + s)*D + d]   (Q, V layouts)
// mode 2: out[((b*H + h)*D + d)*T + s]     (K stored d-major)
// ============================================================================
__global__ __launch_bounds__(256) void gemm_bias_kernel(
    const float* __restrict__ A, const float* __restrict__ W,
    const float* __restrict__ bias, float* __restrict__ Cout,
    int M, int K, int N, int len, int mode)
{
    __shared__ __align__(16) float As2[32][258];  // [k][2m] duplicated, stride even
    __shared__ __align__(16) float Bs [32][68];   // [k][n]

    const int tid = threadIdx.x;
    const int tx = tid & 15;          // n-dim (x4)
    const int ty = tid >> 4;          // m-dim (x8)
    const int tm = blockIdx.y << 7;
    const int tn = blockIdx.x << 6;

    unsigned long long acc[8][2];
#pragma unroll
    for (int i = 0; i < 8; i++) { acc[i][0] = 0ULL; acc[i][1] = 0ULL; }

    for (int k0 = 0; k0 < K; k0 += 32) {
        // Load A tile 128 x 32 (1024 float4), store duplicated-transposed.
#pragma unroll
        for (int i = 0; i < 4; i++) {
            int idx = tid + i * 256;
            int m  = idx >> 3;             // 0..127
            int kb = (idx & 7) << 2;       // 0..28
            float4 av = *(const float4*)(A + (size_t)(tm + m) * K + k0 + kb);
            *(float2*)&As2[kb + 0][m << 1] = make_float2(av.x, av.x);
            *(float2*)&As2[kb + 1][m << 1] = make_float2(av.y, av.y);
            *(float2*)&As2[kb + 2][m << 1] = make_float2(av.z, av.z);
            *(float2*)&As2[kb + 3][m << 1] = make_float2(av.w, av.w);
        }
        // Load B tile 32 x 64 (512 float4)
#pragma unroll
        for (int i = 0; i < 2; i++) {
            int idx = tid + i * 256;
            int kb = idx >> 4;             // 0..31
            int nf = (idx & 15) << 2;      // 0..60
            *(float4*)&Bs[kb][nf] = *(const float4*)(W + (size_t)(k0 + kb) * N + tn + nf);
        }
        __syncthreads();
#pragma unroll
        for (int kk = 0; kk < 32; kk++) {
            ulonglong2 bb = *(const ulonglong2*)&Bs[kk][tx << 2];
#pragma unroll
            for (int i = 0; i < 8; i++) {
                unsigned long long a =
                    *(const unsigned long long*)&As2[kk][((ty << 3) + i) << 1];
                ffma2(acc[i][0], a, bb.x);
                ffma2(acc[i][1], a, bb.y);
            }
        }
        __syncthreads();
    }

#pragma unroll
    for (int i = 0; i < 8; i++) {
        int row = tm + (ty << 3) + i;
#pragma unroll
        for (int j2 = 0; j2 < 2; j2++) {
            float v0, v1;
            unpack2(acc[i][j2], v0, v1);
            int col = tn + (tx << 2) + (j2 << 1);
            v0 += bias[col];
            v1 += bias[col + 1];
            if (mode == 0) {
                Cout[(size_t)row * N + col]     = v0;
                Cout[(size_t)row * N + col + 1] = v1;
            } else {
                int b_ = row / len, s_ = row - b_ * len;
                int h0 = col >> 6, d0 = col & 63;   // col even -> col,col+1 same head
                if (mode == 1) {
                    float* p = Cout + (((size_t)b_ * HH + h0) * len + s_) * DD + d0;
                    p[0] = v0; p[1] = v1;
                } else {
                    float* p = Cout + (((size_t)b_ * HH + h0) * DD + d0) * TT + s_;
                    p[0] = v0; p[TT] = v1;
                }
            }
        }
    }
}

// ============================================================================
// Flash-style attention: one CTA per (b, h, 64-row s-tile). Streams T in
// 64-chunks with online softmax; scores live in registers. Raw scaled scores
// are written to g_praw and per-row (m, invZ/H) to g_stat for the avg kernel.
// smem = 102.9 KB -> 2 CTAs/SM (16 warps).
//
// Layout (floats):
//   sQ2 [64][130]  Q duplicated-transposed: sQ2[d][2s]=(q,q)      8320
//   sK  [64][68]   K chunk, d-major rows                          4352
//   sV  [64][68]   V chunk, t-major rows                          4352
//   sP2 [64][136]  P duplicated: sP2[s][2t]=(p,p)                 8704
// ============================================================================
#define AT_SMEM_FLOATS (8320 + 4352 + 4352 + 8704)
#define AT_SMEM_BYTES  (AT_SMEM_FLOATS * 4)

__global__ __launch_bounds__(256, 2) void attn_flash_kernel(
    const float* __restrict__ q, const float* __restrict__ kdt,
    const float* __restrict__ v, float* __restrict__ ao,
    float* __restrict__ praw, float2* __restrict__ stat)
{
    extern __shared__ __align__(16) float sm[];
    float* sQ2 = sm;
    float* sK  = sm + 8320;
    float* sV  = sm + 12672;
    float* sP2 = sm + 17024;

    const int tid = threadIdx.x;
    const int tx = tid & 15;    // t (phase1) / d (phase3) dim, x4
    const int ty = tid >> 4;    // s dim, x4

    const int bh = blockIdx.x >> 5;              // SS/64 = 32 tiles per head
    const int st = (blockIdx.x & 31) << 6;
    const int b_ = bh >> 4;
    const int h_ = bh & 15;

    const float* qbase = q   + ((size_t)bh * SS + st) * DD;
    const float* kbase = kdt + (size_t)bh * DD * TT;
    const float* vbase = v   + (size_t)bh * TT * DD;

    // Load Q tile [64,64] duplicated-transposed: sQ2[d][2s] = (q,q)
#pragma unroll
    for (int i = 0; i < 4; i++) {
        int idx = tid + i * 256;
        int s_  = idx >> 4;
        int d4  = (idx & 15) << 2;
        float4 qv = *(const float4*)(qbase + (size_t)s_ * DD + d4);
        *(float2*)&sQ2[(d4 + 0) * 130 + (s_ << 1)] = make_float2(qv.x, qv.x);
        *(float2*)&sQ2[(d4 + 1) * 130 + (s_ << 1)] = make_float2(qv.y, qv.y);
        *(float2*)&sQ2[(d4 + 2) * 130 + (s_ << 1)] = make_float2(qv.z, qv.z);
        *(float2*)&sQ2[(d4 + 3) * 130 + (s_ << 1)] = make_float2(qv.w, qv.w);
    }

    unsigned long long oacc[4][2];
    float mrun[4], zrun[4];
#pragma unroll
    for (int i = 0; i < 4; i++) {
        oacc[i][0] = 0ULL; oacc[i][1] = 0ULL;
        mrun[i] = -1e30f;  zrun[i] = 0.f;
    }

    for (int c = 0; c < TT / 64; c++) {
        __syncthreads();   // prev-chunk PV reads of sK/sV done; (iter0: before K/V fill)
        // Load K chunk (d-major) and V chunk (t-major)
#pragma unroll
        for (int i = 0; i < 4; i++) {
            int idx = tid + i * 256;
            int r  = idx >> 4;
            int c4 = (idx & 15) << 2;
            *(float4*)&sK[r * 68 + c4] = *(const float4*)(kbase + (size_t)r * TT + c * 64 + c4);
            *(float4*)&sV[r * 68 + c4] = *(const float4*)(vbase + (size_t)(c * 64 + r) * DD + c4);
        }
        __syncthreads();

        // ---- QK^T chunk: S[64s x 64t], k-depth = 64 d ----
        unsigned long long sacc[4][2] = {{0ULL,0ULL},{0ULL,0ULL},{0ULL,0ULL},{0ULL,0ULL}};
#pragma unroll 16
        for (int kk = 0; kk < 64; kk++) {
            ulonglong2 bb = *(const ulonglong2*)&sK[kk * 68 + (tx << 2)];
#pragma unroll
            for (int i = 0; i < 4; i++) {
                unsigned long long a =
                    *(const unsigned long long*)&sQ2[kk * 130 + (((ty << 2) + i) << 1)];
                ffma2(sacc[i][0], a, bb.x);
                ffma2(sacc[i][1], a, bb.y);
            }
        }

        // ---- online softmax update + raw-score spill + P into smem ----
#pragma unroll
        for (int i = 0; i < 4; i++) {
            float v0, v1, v2, v3;
            unpack2(sacc[i][0], v0, v1);
            unpack2(sacc[i][1], v2, v3);
            v0 *= 0.125f; v1 *= 0.125f; v2 *= 0.125f; v3 *= 0.125f;   // 1/sqrt(64)

            int srow = st + (ty << 2) + i;
            *(float4*)&praw[((size_t)bh * SS + srow) * TT + c * 64 + (tx << 2)] =
                make_float4(v0, v1, v2, v3);

            float cm = fmaxf(fmaxf(v0, v1), fmaxf(v2, v3));
#pragma unroll
            for (int off = 8; off; off >>= 1)
                cm = fmaxf(cm, __shfl_xor_sync(0xffffffffu, cm, off));
            float mn   = fmaxf(mrun[i], cm);
            float corr = __expf(mrun[i] - mn);
            mrun[i] = mn;

            float p0 = __expf(v0 - mn), p1 = __expf(v1 - mn);
            float p2 = __expf(v2 - mn), p3 = __expf(v3 - mn);
            float zs = (p0 + p1) + (p2 + p3);
#pragma unroll
            for (int off = 8; off; off >>= 1)
                zs += __shfl_xor_sync(0xffffffffu, zs, off);
            zrun[i] = zrun[i] * corr + zs;

            unsigned long long cc = pack2(corr, corr);
            fmul2(oacc[i][0], cc);
            fmul2(oacc[i][1], cc);

            float* pp = &sP2[(size_t)((ty << 2) + i) * 136 + (tx << 3)];
            *(float4*)pp       = make_float4(p0, p0, p1, p1);
            *(float4*)(pp + 4) = make_float4(p2, p2, p3, p3);
        }
        __syncwarp();   // sP2 rows are produced & consumed within one half-warp

        // ---- PV chunk: out += P[64s x 64t] @ V[64t x 64d] ----
#pragma unroll 16
        for (int kk = 0; kk < 64; kk++) {
            ulonglong2 vv = *(const ulonglong2*)&sV[kk * 68 + (tx << 2)];
#pragma unroll
            for (int i = 0; i < 4; i++) {
                unsigned long long a =
                    *(const unsigned long long*)&sP2[(size_t)((ty << 2) + i) * 136 + (kk << 1)];
                ffma2(oacc[i][0], a, vv.x);
                ffma2(oacc[i][1], a, vv.y);
            }
        }
    }

    // ---- epilogue: normalize, write out head-slice + per-row stats ----
#pragma unroll
    for (int i = 0; i < 4; i++) {
        float inv = 1.0f / zrun[i];
        float v0, v1, v2, v3;
        unpack2(oacc[i][0], v0, v1);
        unpack2(oacc[i][1], v2, v3);
        int srow = st + (ty << 2) + i;
        float* p = ao + ((size_t)b_ * SS + srow) * EE + h_ * DD + (tx << 2);
        *(float4*)p = make_float4(v0 * inv, v1 * inv, v2 * inv, v3 * inv);
        if (tx == 0)
            stat[(size_t)bh * SS + srow] = make_float2(mrun[i], inv * (1.0f / (float)HH));
    }
}

// ============================================================================
// avg_attn: avg[b,s,t] = (1/H) sum_h exp(praw[b,h,s,t] - m[bh,s]) * invZ[bh,s]
// Pure memory-bound pass over 1.07 GB; no atomics.
// ============================================================================
__global__ __launch_bounds__(256) void avg_kernel(
    const float* __restrict__ praw, const float2* __restrict__ stat,
    float* __restrict__ avg)
{
    size_t gi = (size_t)blockIdx.x * 256 + threadIdx.x;    // over B*S*(T/4)
    int    t4 = (int)(gi & (TT / 4 - 1)) << 2;
    size_t bs = gi >> 8;                                    // / (T/4)
    int b_ = (int)(bs >> 11);                               // / SS
    int s_ = (int)(bs & (SS - 1));

    float a0 = 0.f, a1 = 0.f, a2 = 0.f, a3 = 0.f;
#pragma unroll
    for (int h = 0; h < HH; h++) {
        size_t row = ((size_t)(b_ * HH + h) * SS + s_);
        float2 mz = stat[row];
        float4 r  = *(const float4*)&praw[row * TT + t4];
        a0 += __expf(r.x - mz.x) * mz.y;
        a1 += __expf(r.y - mz.x) * mz.y;
        a2 += __expf(r.z - mz.x) * mz.y;
        a3 += __expf(r.w - mz.x) * mz.y;
    }
    *(float4*)&avg[bs * TT + t4] = make_float4(a0, a1, a2, a3);
}

// ============================================================================
// Launch
// ============================================================================
extern "C" void kernel_launch(void* const* d_in, const int* in_sizes, int n_in,
                              void* d_out, int out_size)
{
    const float* x   = (const float*)d_in[0];
    const float* enc = (const float*)d_in[1];
    const float* Wq  = (const float*)d_in[2];
    const float* bq  = (const float*)d_in[3];
    const float* Wk  = (const float*)d_in[4];
    const float* bk  = (const float*)d_in[5];
    const float* Wv  = (const float*)d_in[6];
    const float* bv  = (const float*)d_in[7];
    const float* Wo  = (const float*)d_in[8];
    const float* bo  = (const float*)d_in[9];

    float* out = (float*)d_out;                       // [B,S,E]
    float* avg = out + (size_t)BB * SS * EE;          // [B,S,T]

    float *qp, *kp, *vp, *aop, *prp;
    float2* stp;
    cudaGetSymbolAddress((void**)&qp,  g_q);
    cudaGetSymbolAddress((void**)&kp,  g_k);
    cudaGetSymbolAddress((void**)&vp,  g_v);
    cudaGetSymbolAddress((void**)&aop, g_ao);
    cudaGetSymbolAddress((void**)&prp, g_praw);
    cudaGetSymbolAddress((void**)&stp, g_stat);

    cudaFuncSetAttribute(attn_flash_kernel,
                         cudaFuncAttributeMaxDynamicSharedMemorySize, AT_SMEM_BYTES);

    // Q = x @ Wq + bq        -> [B,H,S,D]
    gemm_bias_kernel<<<dim3(EE / 64, (BB * SS) / 128), 256>>>(x,   Wq, bq, qp,  BB * SS, EE, EE, SS, 1);
    // K = enc @ Wk + bk      -> [B,H,D,T] (d-major)
    gemm_bias_kernel<<<dim3(EE / 64, (BB * TT) / 128), 256>>>(enc, Wk, bk, kp,  BB * TT, CC, EE, TT, 2);
    // V = enc @ Wv + bv      -> [B,H,T,D]
    gemm_bias_kernel<<<dim3(EE / 64, (BB * TT) / 128), 256>>>(enc, Wv, bv, vp,  BB * TT, CC, EE, TT, 1);
    // flash attention (writes g_ao, g_praw, g_stat)
    attn_flash_kernel<<<BB * HH * (SS / 64), 256, AT_SMEM_BYTES>>>(qp, kp, vp, aop, prp, stp);
    // avg_attn from raw scores + stats
    avg_kernel<<<(unsigned)((size_t)BB * SS * (TT / 4) / 256), 256>>>(prp, stp, avg);
    // out = attn_out @ Wo + bo
    gemm_bias_kernel<<<dim3(EE / 64, (BB * SS) / 128), 256>>>(aop, Wo, bo, out, BB * SS, EE, EE, 0, 0);
}

// round 7
// speedup vs baseline: 1.0017x; 1.0017x over previous
#include <cuda_runtime.h>
#include <cstdint>
#include <cstddef>

#define BB 8
#define SS 2048
#define TT 1024
#define EE 1024
#define HH 16
#define DD 64
#define CC 768

// Scratch (device globals: allocation-free rule)
__device__ float  g_q   [(size_t)BB*HH*SS*DD];   // [B,H,S,D]  64 MB
__device__ float  g_k   [(size_t)BB*HH*DD*TT];   // [B,H,D,T]  32 MB
__device__ float  g_v   [(size_t)BB*HH*TT*DD];   // [B,H,T,D]  32 MB
__device__ float  g_ao  [(size_t)BB*SS*EE];      // attn out [B,S,E] 64 MB
__device__ float  g_praw[(size_t)BB*HH*SS*TT];   // raw scaled scores [B,H,S,T] 1 GiB
__device__ float2 g_stat[(size_t)BB*HH*SS];      // per-row (m, invZ/H) 2 MB

// ---- packed f32x2 helpers ----
__device__ __forceinline__ unsigned long long pack2(float lo, float hi) {
    unsigned long long r;
    asm("mov.b64 %0, {%1, %2};" : "=l"(r) : "f"(lo), "f"(hi));
    return r;
}
__device__ __forceinline__ void unpack2(unsigned long long v, float& lo, float& hi) {
    asm("mov.b64 {%0, %1}, %2;" : "=f"(lo), "=f"(hi) : "l"(v));
}
__device__ __forceinline__ void ffma2(unsigned long long& d, unsigned long long a, unsigned long long b) {
    asm("fma.rn.f32x2 %0, %1, %2, %0;" : "+l"(d) : "l"(a), "l"(b));
}
__device__ __forceinline__ void fmul2(unsigned long long& d, unsigned long long a) {
    asm("mul.rn.f32x2 %0, %0, %1;" : "+l"(d) : "l"(a));
}

// ============================================================================
// GEMM v2: C[M,N] = A[M,K] @ W[K,N] + bias, head-remapped output.
// 128x64 CTA tile, 256 threads, 8(m)x4(n) micro-tile, K-chunk 32.
// A stored DUPLICATED in smem: As2[k][2m]=As2[k][2m+1]=a  -> LDS.64 gives (a,a)
// directly, zero mov.b64 packs in the inner loop. B read as natural f32x2
// pairs via LDS.128.
// mode 0: plain row-major [M,N]
// mode 1: out[((b*H + h)*len + s)*D + d]   (Q, V layouts)
// mode 2: out[((b*H + h)*D + d)*T + s]     (K stored d-major)
// ============================================================================
__global__ __launch_bounds__(256) void gemm_bias_kernel(
    const float* __restrict__ A, const float* __restrict__ W,
    const float* __restrict__ bias, float* __restrict__ Cout,
    int M, int K, int N, int len, int mode)
{
    __shared__ __align__(16) float As2[32][258];  // [k][2m] duplicated, stride even
    __shared__ __align__(16) float Bs [32][68];   // [k][n]

    const int tid = threadIdx.x;
    const int tx = tid & 15;          // n-dim (x4)
    const int ty = tid >> 4;          // m-dim (x8)
    const int tm = blockIdx.y << 7;
    const int tn = blockIdx.x << 6;

    unsigned long long acc[8][2];
#pragma unroll
    for (int i = 0; i < 8; i++) { acc[i][0] = 0ULL; acc[i][1] = 0ULL; }

    for (int k0 = 0; k0 < K; k0 += 32) {
        // Load A tile 128 x 32 (1024 float4), store duplicated-transposed.
#pragma unroll
        for (int i = 0; i < 4; i++) {
            int idx = tid + i * 256;
            int m  = idx >> 3;             // 0..127
            int kb = (idx & 7) << 2;       // 0..28
            float4 av = *(const float4*)(A + (size_t)(tm + m) * K + k0 + kb);
            *(float2*)&As2[kb + 0][m << 1] = make_float2(av.x, av.x);
            *(float2*)&As2[kb + 1][m << 1] = make_float2(av.y, av.y);
            *(float2*)&As2[kb + 2][m << 1] = make_float2(av.z, av.z);
            *(float2*)&As2[kb + 3][m << 1] = make_float2(av.w, av.w);
        }
        // Load B tile 32 x 64 (512 float4)
#pragma unroll
        for (int i = 0; i < 2; i++) {
            int idx = tid + i * 256;
            int kb = idx >> 4;             // 0..31
            int nf = (idx & 15) << 2;      // 0..60
            *(float4*)&Bs[kb][nf] = *(const float4*)(W + (size_t)(k0 + kb) * N + tn + nf);
        }
        __syncthreads();
#pragma unroll
        for (int kk = 0; kk < 32; kk++) {
            ulonglong2 bb = *(const ulonglong2*)&Bs[kk][tx << 2];
#pragma unroll
            for (int i = 0; i < 8; i++) {
                unsigned long long a =
                    *(const unsigned long long*)&As2[kk][((ty << 3) + i) << 1];
                ffma2(acc[i][0], a, bb.x);
                ffma2(acc[i][1], a, bb.y);
            }
        }
        __syncthreads();
    }

#pragma unroll
    for (int i = 0; i < 8; i++) {
        int row = tm + (ty << 3) + i;
#pragma unroll
        for (int j2 = 0; j2 < 2; j2++) {
            float v0, v1;
            unpack2(acc[i][j2], v0, v1);
            int col = tn + (tx << 2) + (j2 << 1);
            v0 += bias[col];
            v1 += bias[col + 1];
            if (mode == 0) {
                Cout[(size_t)row * N + col]     = v0;
                Cout[(size_t)row * N + col + 1] = v1;
            } else {
                int b_ = row / len, s_ = row - b_ * len;
                int h0 = col >> 6, d0 = col & 63;   // col even -> col,col+1 same head
                if (mode == 1) {
                    float* p = Cout + (((size_t)b_ * HH + h0) * len + s_) * DD + d0;
                    p[0] = v0; p[1] = v1;
                } else {
                    float* p = Cout + (((size_t)b_ * HH + h0) * DD + d0) * TT + s_;
                    p[0] = v0; p[TT] = v1;
                }
            }
        }
    }
}

// ============================================================================
// Flash-style attention: one CTA per (b, h, 64-row s-tile). Streams T in
// 64-chunks with online softmax; scores live in registers. Raw scaled scores
// are written to g_praw and per-row (m, invZ/H) to g_stat for the avg kernel.
// smem = 102.9 KB -> 2 CTAs/SM (16 warps).
//
// Layout (floats):
//   sQ2 [64][130]  Q duplicated-transposed: sQ2[d][2s]=(q,q)      8320
//   sK  [64][68]   K chunk, d-major rows                          4352
//   sV  [64][68]   V chunk, t-major rows                          4352
//   sP2 [64][136]  P duplicated: sP2[s][2t]=(p,p)                 8704
// ============================================================================
#define AT_SMEM_FLOATS (8320 + 4352 + 4352 + 8704)
#define AT_SMEM_BYTES  (AT_SMEM_FLOATS * 4)

__global__ __launch_bounds__(256, 2) void attn_flash_kernel(
    const float* __restrict__ q, const float* __restrict__ kdt,
    const float* __restrict__ v, float* __restrict__ ao,
    float* __restrict__ praw, float2* __restrict__ stat)
{
    extern __shared__ __align__(16) float sm[];
    float* sQ2 = sm;
    float* sK  = sm + 8320;
    float* sV  = sm + 12672;
    float* sP2 = sm + 17024;

    const int tid = threadIdx.x;
    const int tx = tid & 15;    // t (phase1) / d (phase3) dim, x4
    const int ty = tid >> 4;    // s dim, x4

    const int bh = blockIdx.x >> 5;              // SS/64 = 32 tiles per head
    const int st = (blockIdx.x & 31) << 6;
    const int b_ = bh >> 4;
    const int h_ = bh & 15;

    const float* qbase = q   + ((size_t)bh * SS + st) * DD;
    const float* kbase = kdt + (size_t)bh * DD * TT;
    const float* vbase = v   + (size_t)bh * TT * DD;

    // Load Q tile [64,64] duplicated-transposed: sQ2[d][2s] = (q,q)
#pragma unroll
    for (int i = 0; i < 4; i++) {
        int idx = tid + i * 256;
        int s_  = idx >> 4;
        int d4  = (idx & 15) << 2;
        float4 qv = *(const float4*)(qbase + (size_t)s_ * DD + d4);
        *(float2*)&sQ2[(d4 + 0) * 130 + (s_ << 1)] = make_float2(qv.x, qv.x);
        *(float2*)&sQ2[(d4 + 1) * 130 + (s_ << 1)] = make_float2(qv.y, qv.y);
        *(float2*)&sQ2[(d4 + 2) * 130 + (s_ << 1)] = make_float2(qv.z, qv.z);
        *(float2*)&sQ2[(d4 + 3) * 130 + (s_ << 1)] = make_float2(qv.w, qv.w);
    }

    unsigned long long oacc[4][2];
    float mrun[4], zrun[4];
#pragma unroll
    for (int i = 0; i < 4; i++) {
        oacc[i][0] = 0ULL; oacc[i][1] = 0ULL;
        mrun[i] = -1e30f;  zrun[i] = 0.f;
    }

    for (int c = 0; c < TT / 64; c++) {
        __syncthreads();   // prev-chunk PV reads of sK/sV done; (iter0: before K/V fill)
        // Load K chunk (d-major) and V chunk (t-major)
#pragma unroll
        for (int i = 0; i < 4; i++) {
            int idx = tid + i * 256;
            int r  = idx >> 4;
            int c4 = (idx & 15) << 2;
            *(float4*)&sK[r * 68 + c4] = *(const float4*)(kbase + (size_t)r * TT + c * 64 + c4);
            *(float4*)&sV[r * 68 + c4] = *(const float4*)(vbase + (size_t)(c * 64 + r) * DD + c4);
        }
        __syncthreads();

        // ---- QK^T chunk: S[64s x 64t], k-depth = 64 d ----
        unsigned long long sacc[4][2] = {{0ULL,0ULL},{0ULL,0ULL},{0ULL,0ULL},{0ULL,0ULL}};
#pragma unroll 16
        for (int kk = 0; kk < 64; kk++) {
            ulonglong2 bb = *(const ulonglong2*)&sK[kk * 68 + (tx << 2)];
#pragma unroll
            for (int i = 0; i < 4; i++) {
                unsigned long long a =
                    *(const unsigned long long*)&sQ2[kk * 130 + (((ty << 2) + i) << 1)];
                ffma2(sacc[i][0], a, bb.x);
                ffma2(sacc[i][1], a, bb.y);
            }
        }

        // ---- online softmax update + raw-score spill + P into smem ----
#pragma unroll
        for (int i = 0; i < 4; i++) {
            float v0, v1, v2, v3;
            unpack2(sacc[i][0], v0, v1);
            unpack2(sacc[i][1], v2, v3);
            v0 *= 0.125f; v1 *= 0.125f; v2 *= 0.125f; v3 *= 0.125f;   // 1/sqrt(64)

            int srow = st + (ty << 2) + i;
            *(float4*)&praw[((size_t)bh * SS + srow) * TT + c * 64 + (tx << 2)] =
                make_float4(v0, v1, v2, v3);

            float cm = fmaxf(fmaxf(v0, v1), fmaxf(v2, v3));
#pragma unroll
            for (int off = 8; off; off >>= 1)
                cm = fmaxf(cm, __shfl_xor_sync(0xffffffffu, cm, off));
            float mn   = fmaxf(mrun[i], cm);
            float corr = __expf(mrun[i] - mn);
            mrun[i] = mn;

            float p0 = __expf(v0 - mn), p1 = __expf(v1 - mn);
            float p2 = __expf(v2 - mn), p3 = __expf(v3 - mn);
            float zs = (p0 + p1) + (p2 + p3);
#pragma unroll
            for (int off = 8; off; off >>= 1)
                zs += __shfl_xor_sync(0xffffffffu, zs, off);
            zrun[i] = zrun[i] * corr + zs;

            unsigned long long cc = pack2(corr, corr);
            fmul2(oacc[i][0], cc);
            fmul2(oacc[i][1], cc);

            float* pp = &sP2[(size_t)((ty << 2) + i) * 136 + (tx << 3)];
            *(float4*)pp       = make_float4(p0, p0, p1, p1);
            *(float4*)(pp + 4) = make_float4(p2, p2, p3, p3);
        }
        __syncwarp();   // sP2 rows are produced & consumed within one half-warp

        // ---- PV chunk: out += P[64s x 64t] @ V[64t x 64d] ----
#pragma unroll 16
        for (int kk = 0; kk < 64; kk++) {
            ulonglong2 vv = *(const ulonglong2*)&sV[kk * 68 + (tx << 2)];
#pragma unroll
            for (int i = 0; i < 4; i++) {
                unsigned long long a =
                    *(const unsigned long long*)&sP2[(size_t)((ty << 2) + i) * 136 + (kk << 1)];
                ffma2(oacc[i][0], a, vv.x);
                ffma2(oacc[i][1], a, vv.y);
            }
        }
    }

    // ---- epilogue: normalize, write out head-slice + per-row stats ----
#pragma unroll
    for (int i = 0; i < 4; i++) {
        float inv = 1.0f / zrun[i];
        float v0, v1, v2, v3;
        unpack2(oacc[i][0], v0, v1);
        unpack2(oacc[i][1], v2, v3);
        int srow = st + (ty << 2) + i;
        float* p = ao + ((size_t)b_ * SS + srow) * EE + h_ * DD + (tx << 2);
        *(float4*)p = make_float4(v0 * inv, v1 * inv, v2 * inv, v3 * inv);
        if (tx == 0)
            stat[(size_t)bh * SS + srow] = make_float2(mrun[i], inv * (1.0f / (float)HH));
    }
}

// ============================================================================
// avg_attn: avg[b,s,t] = (1/H) sum_h exp(praw[b,h,s,t] - m[bh,s]) * invZ[bh,s]
// Pure memory-bound pass over 1.07 GB; no atomics.
// ============================================================================
__global__ __launch_bounds__(256) void avg_kernel(
    const float* __restrict__ praw, const float2* __restrict__ stat,
    float* __restrict__ avg)
{
    size_t gi = (size_t)blockIdx.x * 256 + threadIdx.x;    // over B*S*(T/4)
    int    t4 = (int)(gi & (TT / 4 - 1)) << 2;
    size_t bs = gi >> 8;                                    // / (T/4)
    int b_ = (int)(bs >> 11);                               // / SS
    int s_ = (int)(bs & (SS - 1));

    float a0 = 0.f, a1 = 0.f, a2 = 0.f, a3 = 0.f;
#pragma unroll
    for (int h = 0; h < HH; h++) {
        size_t row = ((size_t)(b_ * HH + h) * SS + s_);
        float2 mz = stat[row];
        float4 r  = *(const float4*)&praw[row * TT + t4];
        a0 += __expf(r.x - mz.x) * mz.y;
        a1 += __expf(r.y - mz.x) * mz.y;
        a2 += __expf(r.z - mz.x) * mz.y;
        a3 += __expf(r.w - mz.x) * mz.y;
    }
    *(float4*)&avg[bs * TT + t4] = make_float4(a0, a1, a2, a3);
}

// ============================================================================
// Launch
// ============================================================================
extern "C" void kernel_launch(void* const* d_in, const int* in_sizes, int n_in,
                              void* d_out, int out_size)
{
    const float* x   = (const float*)d_in[0];
    const float* enc = (const float*)d_in[1];
    const float* Wq  = (const float*)d_in[2];
    const float* bq  = (const float*)d_in[3];
    const float* Wk  = (const float*)d_in[4];
    const float* bk  = (const float*)d_in[5];
    const float* Wv  = (const float*)d_in[6];
    const float* bv  = (const float*)d_in[7];
    const float* Wo  = (const float*)d_in[8];
    const float* bo  = (const float*)d_in[9];

    float* out = (float*)d_out;                       // [B,S,E]
    float* avg = out + (size_t)BB * SS * EE;          // [B,S,T]

    float *qp, *kp, *vp, *aop, *prp;
    float2* stp;
    cudaGetSymbolAddress((void**)&qp,  g_q);
    cudaGetSymbolAddress((void**)&kp,  g_k);
    cudaGetSymbolAddress((void**)&vp,  g_v);
    cudaGetSymbolAddress((void**)&aop, g_ao);
    cudaGetSymbolAddress((void**)&prp, g_praw);
    cudaGetSymbolAddress((void**)&stp, g_stat);

    cudaFuncSetAttribute(attn_flash_kernel,
                         cudaFuncAttributeMaxDynamicSharedMemorySize, AT_SMEM_BYTES);

    // Q = x @ Wq + bq        -> [B,H,S,D]
    gemm_bias_kernel<<<dim3(EE / 64, (BB * SS) / 128), 256>>>(x,   Wq, bq, qp,  BB * SS, EE, EE, SS, 1);
    // K = enc @ Wk + bk      -> [B,H,D,T] (d-major)
    gemm_bias_kernel<<<dim3(EE / 64, (BB * TT) / 128), 256>>>(enc, Wk, bk, kp,  BB * TT, CC, EE, TT, 2);
    // V = enc @ Wv + bv      -> [B,H,T,D]
    gemm_bias_kernel<<<dim3(EE / 64, (BB * TT) / 128), 256>>>(enc, Wv, bv, vp,  BB * TT, CC, EE, TT, 1);
    // flash attention (writes g_ao, g_praw, g_stat)
    attn_flash_kernel<<<BB * HH * (SS / 64), 256, AT_SMEM_BYTES>>>(qp, kp, vp, aop, prp, stp);
    // avg_attn from raw scores + stats
    avg_kernel<<<(unsigned)((size_t)BB * SS * (TT / 4) / 256), 256>>>(prp, stp, avg);
    // out = attn_out @ Wo + bo
    gemm_bias_kernel<<<dim3(EE / 64, (BB * SS) / 128), 256>>>(aop, Wo, bo, out, BB * SS, EE, EE, 0, 0);
}